// round 6
// baseline (speedup 1.0000x reference)
#include <cuda_runtime.h>
#include <cuda_fp16.h>
#include <cstdint>
#include <cstddef>

// ============================================================================
// QuaternionLinear == one dense GEMM: C[32768,1024] = X[32768,1024] @ W^T
//   W[4o+oc, 4i+ic] = S[oc][ic] * w_{T[oc][ic]}[o,i]
// compute_103 PTX rejects tcgen05.* -> cp.async + ldmatrix + mma.sync (HMMA).
// R5: CTA 128x256, 512 threads, warp tile 64x32 (2x8 warp grid), 2 stages,
// 2 CTAs/SM (97KB smem). Crossbar 1875 cyc < tensor 2048 cyc per chunk ->
// tensor-bound; 8 warps/SMSP for latency hiding.
// ============================================================================

#define IN_F    1024
#define OUT_F   1024
#define M_TOTAL 32768

__device__ __half g_W[(size_t)OUT_F * IN_F];            // 2 MB
__device__ __half g_X[(size_t)M_TOTAL * IN_F];          // 64 MB scratch

__constant__ int   c_T[16] = {0,1,2,3,  1,0,3,2,  2,3,0,1,  3,2,1,0};
__constant__ float c_S[16] = {1,-1,-1,-1,  1,1,1,-1,  1,-1,1,1,  1,1,-1,1};

// --------------------------------------------------------------------------
// Fused prologue: blocks [0, 1024) build W; blocks [1024, 17408) convert X.
// --------------------------------------------------------------------------
constexpr int WBLOCKS = OUT_F * 256 / 256;                    // 1024
constexpr int XBLOCKS = (M_TOTAL * IN_F / 8) / 256;           // 16384

__global__ void prologue_kernel(const float* __restrict__ rw, const float* __restrict__ iw,
                                const float* __restrict__ jw, const float* __restrict__ kw,
                                const float* __restrict__ x) {
    if (blockIdx.x < WBLOCKS) {
        int idx = blockIdx.x * 256 + threadIdx.x;   // idx = n*256 + i
        int n = idx >> 8;
        int i = idx & 255;
        int o = n >> 2, oc = n & 3;
        const float* ws[4] = {rw, iw, jw, kw};
        float v0 = c_S[oc*4+0] * ws[c_T[oc*4+0]][o*256 + i];
        float v1 = c_S[oc*4+1] * ws[c_T[oc*4+1]][o*256 + i];
        float v2 = c_S[oc*4+2] * ws[c_T[oc*4+2]][o*256 + i];
        float v3 = c_S[oc*4+3] * ws[c_T[oc*4+3]][o*256 + i];
        __half2 h01 = __floats2half2_rn(v0, v1);
        __half2 h23 = __floats2half2_rn(v2, v3);
        uint2 p;
        p.x = *reinterpret_cast<uint32_t*>(&h01);
        p.y = *reinterpret_cast<uint32_t*>(&h23);
        *reinterpret_cast<uint2*>(&g_W[(size_t)n * IN_F + 4 * i]) = p;
    } else {
        size_t i = ((size_t)(blockIdx.x - WBLOCKS) * 256 + threadIdx.x) * 2;  // float4 idx
        #pragma unroll
        for (int j = 0; j < 2; j++) {
            float4 f = reinterpret_cast<const float4*>(x)[i + j];
            __half2 h0 = __floats2half2_rn(f.x, f.y);
            __half2 h1 = __floats2half2_rn(f.z, f.w);
            uint2 p;
            p.x = *reinterpret_cast<uint32_t*>(&h0);
            p.y = *reinterpret_cast<uint32_t*>(&h1);
            reinterpret_cast<uint2*>(g_X)[i + j] = p;
        }
    }
}

// --------------------------------------------------------------------------
// helpers
// --------------------------------------------------------------------------
__device__ __forceinline__ uint32_t smem_u32(const void* p) {
    uint32_t a;
    asm("{ .reg .u64 t; cvta.to.shared.u64 t, %1; cvt.u32.u64 %0, t; }" : "=r"(a) : "l"(p));
    return a;
}

__device__ __forceinline__ void cp_async16(uint32_t saddr, const void* gptr) {
    asm volatile("cp.async.cg.shared.global [%0], [%1], 16;" :: "r"(saddr), "l"(gptr));
}

#define CP_COMMIT() asm volatile("cp.async.commit_group;" ::: "memory")
#define CP_WAIT1()  asm volatile("cp.async.wait_group 1;" ::: "memory")

#define LDSM4(r, addr)                                                         \
    asm volatile("ldmatrix.sync.aligned.m8n8.x4.shared.b16 {%0,%1,%2,%3}, [%4];" \
                 : "=r"((r)[0]), "=r"((r)[1]), "=r"((r)[2]), "=r"((r)[3])       \
                 : "r"(addr))

#define MMA16816(c, a, b0, b1)                                                 \
    asm volatile("mma.sync.aligned.m16n8k16.row.col.f32.f16.f16.f32 "          \
                 "{%0,%1,%2,%3}, {%4,%5,%6,%7}, {%8,%9}, {%0,%1,%2,%3};"       \
                 : "+f"((c)[0]), "+f"((c)[1]), "+f"((c)[2]), "+f"((c)[3])      \
                 : "r"((a)[0]), "r"((a)[1]), "r"((a)[2]), "r"((a)[3]),         \
                   "r"(b0), "r"(b1))

__device__ __forceinline__ uint32_t swz(uint32_t off) {
    return off ^ ((off >> 3) & 0x70u);   // 128B-row XOR swizzle
}

// --------------------------------------------------------------------------
// GEMM config: CTA 128x256, 512 thr, warp tile 64x32 (2x8), BK=64, 2 stages
// --------------------------------------------------------------------------
constexpr int BM = 128, BN = 256, BK = 64;
constexpr int NCHUNK = IN_F / BK;          // 16
constexpr int ASTG = BM * BK * 2;          // 16384 B
constexpr int BSTG = BN * BK * 2;          // 32768 B
constexpr int STAGES = 2;
constexpr int SM_B    = STAGES * ASTG;               // 32768
constexpr int SM_BIAS = SM_B + STAGES * BSTG;        // 98304
constexpr int SM_TOTAL = SM_BIAS + 1024;             // 99328 -> 2 CTAs/SM

__global__ void __launch_bounds__(512, 2)
qgemm(const float* __restrict__ bias, float* __restrict__ out) {
    extern __shared__ __align__(1024) char smem[];
    const uint32_t sb = smem_u32(smem);
    const int tid  = threadIdx.x;
    const int lane = tid & 31;
    const int wid  = tid >> 5;
    const int warp_m = wid >> 3;            // 0..1  (64 rows each)
    const int warp_n = wid & 7;             // 0..7  (32 cols each)
    const int m_base = blockIdx.y * BM;
    const int n_base = blockIdx.x * BN;

    if (tid < 256) reinterpret_cast<float*>(smem + SM_BIAS)[tid] = bias[n_base + tid];

    // cp.async geometry: 512 threads, 16B per op, 128B rows, 64 rows/round
    const int seg  = tid & 7;               // 8 segs per 128B row
    const int row0 = tid >> 3;              // 0..63

    auto load_chunk = [&](int s, int c) {
        const int k0 = c * BK;
        const __half* ga = g_X + (size_t)m_base * IN_F + k0 + seg * 8;
        const __half* gb = g_W + (size_t)n_base * IN_F + k0 + seg * 8;
        const uint32_t sA  = sb + s * ASTG;
        const uint32_t sB2 = sb + SM_B + s * BSTG;
        #pragma unroll
        for (int r = 0; r < 2; r++) {       // A: 128 rows
            int row = row0 + r * 64;
            uint32_t off = swz((uint32_t)row * 128u + (uint32_t)seg * 16u);
            cp_async16(sA + off, ga + (size_t)row * IN_F);
        }
        #pragma unroll
        for (int r = 0; r < 4; r++) {       // B: 256 rows
            int row = row0 + r * 64;
            uint32_t off = swz((uint32_t)row * 128u + (uint32_t)seg * 16u);
            cp_async16(sB2 + off, gb + (size_t)row * IN_F);
        }
    };

    float acc[4][4][4] = {};

    load_chunk(0, 0);
    CP_COMMIT();

    #pragma unroll 1
    for (int c = 0; c < NCHUNK; c++) {
        if (c + 1 < NCHUNK) { load_chunk((c + 1) & 1, c + 1); }
        CP_COMMIT();
        CP_WAIT1();          // chunk c resident
        __syncthreads();

        const int s = c & 1;
        const uint32_t sA  = sb + s * ASTG;
        const uint32_t sB2 = sb + SM_B + s * BSTG;

        #pragma unroll
        for (int ks = 0; ks < 4; ks++) {
            uint32_t a[4][4], b[2][4];
            #pragma unroll
            for (int mt = 0; mt < 4; mt++) {
                int row = warp_m * 64 + mt * 16 + (lane & 15);
                int col = ks * 16 + (lane >> 4) * 8;
                LDSM4(a[mt], sA + swz((uint32_t)row * 128u + (uint32_t)col * 2u));
            }
            #pragma unroll
            for (int nt = 0; nt < 2; nt++) {
                int row = warp_n * 32 + nt * 16 + (lane & 7) + ((lane >> 4) & 1) * 8;
                int col = ks * 16 + ((lane >> 3) & 1) * 8;
                LDSM4(b[nt], sB2 + swz((uint32_t)row * 128u + (uint32_t)col * 2u));
            }
            #pragma unroll
            for (int mt = 0; mt < 4; mt++) {
                #pragma unroll
                for (int no = 0; no < 4; no++) {
                    MMA16816(acc[mt][no], a[mt],
                             b[no >> 1][(no & 1) * 2], b[no >> 1][(no & 1) * 2 + 1]);
                }
            }
        }
        __syncthreads();     // all reads of buf s done before it is refilled
    }

    // epilogue: direct float2 stores + bias
    const float* sbias = reinterpret_cast<const float*>(smem + SM_BIAS);
    #pragma unroll
    for (int mt = 0; mt < 4; mt++) {
        int r0 = m_base + warp_m * 64 + mt * 16 + (lane >> 2);
        #pragma unroll
        for (int no = 0; no < 4; no++) {
            int cl = warp_n * 32 + no * 8 + (lane & 3) * 2;   // local col
            float b0 = sbias[cl], b1 = sbias[cl + 1];
            float2 v0 = make_float2(acc[mt][no][0] + b0, acc[mt][no][1] + b1);
            float2 v1 = make_float2(acc[mt][no][2] + b0, acc[mt][no][3] + b1);
            *reinterpret_cast<float2*>(out + (size_t)r0 * OUT_F + n_base + cl)       = v0;
            *reinterpret_cast<float2*>(out + (size_t)(r0 + 8) * OUT_F + n_base + cl) = v1;
        }
    }
}

// --------------------------------------------------------------------------
extern "C" void kernel_launch(void* const* d_in, const int* in_sizes, int n_in,
                              void* d_out, int out_size) {
    const float* x    = (const float*)d_in[0];
    const float* rw   = (const float*)d_in[1];
    const float* iw   = (const float*)d_in[2];
    const float* jw   = (const float*)d_in[3];
    const float* kw   = (const float*)d_in[4];
    const float* bias = (const float*)d_in[5];
    float* out = (float*)d_out;

    static bool attr_done = false;
    if (!attr_done) {
        cudaFuncSetAttribute(qgemm, cudaFuncAttributeMaxDynamicSharedMemorySize, SM_TOTAL);
        attr_done = true;
    }

    prologue_kernel<<<WBLOCKS + XBLOCKS, 256>>>(rw, iw, jw, kw, x);

    dim3 grid(OUT_F / BN, M_TOTAL / BM);   // (4, 256): N fastest -> A-tile L2 reuse
    qgemm<<<grid, 512, SM_TOTAL>>>(bias, out);
}

// round 7
// speedup vs baseline: 2.8731x; 2.8731x over previous
#include <cuda_runtime.h>
#include <cuda_fp16.h>
#include <cstdint>
#include <cstddef>

// ============================================================================
// QuaternionLinear == one dense GEMM: C[32768,1024] = X[32768,1024] @ W^T
//   W[4o+oc, 4i+ic] = S[oc][ic] * w_{T[oc][ic]}[o,i]
// compute_103 PTX rejects tcgen05.* -> cp.async + ldmatrix + mma.sync (HMMA).
// R7: R4 geometry (CTA 128x128, warp 64x32, BK=64, 3 stages, 2 CTAs/SM,
// 124 regs) + fused A fp32->fp16 conversion inside the GEMM (no g_X scratch
// pass) + loads issued before the stage wait. Reg-file caps occupancy at
// 2x256thr (R5 spill lesson: never exceed ~128 regs/thread here).
// ============================================================================

#define IN_F    1024
#define OUT_F   1024
#define M_TOTAL 32768

__device__ __half g_W[(size_t)OUT_F * IN_F];            // 2 MB

__constant__ int   c_T[16] = {0,1,2,3,  1,0,3,2,  2,3,0,1,  3,2,1,0};
__constant__ float c_S[16] = {1,-1,-1,-1,  1,1,1,-1,  1,-1,1,1,  1,1,-1,1};

// --------------------------------------------------------------------------
// Prologue: build W fp16 only (X is converted inside the GEMM now).
// --------------------------------------------------------------------------
__global__ void build_w_kernel(const float* __restrict__ rw, const float* __restrict__ iw,
                               const float* __restrict__ jw, const float* __restrict__ kw) {
    int idx = blockIdx.x * 256 + threadIdx.x;   // idx = n*256 + i
    int n = idx >> 8;
    int i = idx & 255;
    int o = n >> 2, oc = n & 3;
    const float* ws[4] = {rw, iw, jw, kw};
    float v0 = c_S[oc*4+0] * ws[c_T[oc*4+0]][o*256 + i];
    float v1 = c_S[oc*4+1] * ws[c_T[oc*4+1]][o*256 + i];
    float v2 = c_S[oc*4+2] * ws[c_T[oc*4+2]][o*256 + i];
    float v3 = c_S[oc*4+3] * ws[c_T[oc*4+3]][o*256 + i];
    __half2 h01 = __floats2half2_rn(v0, v1);
    __half2 h23 = __floats2half2_rn(v2, v3);
    uint2 p;
    p.x = *reinterpret_cast<uint32_t*>(&h01);
    p.y = *reinterpret_cast<uint32_t*>(&h23);
    *reinterpret_cast<uint2*>(&g_W[(size_t)n * IN_F + 4 * i]) = p;
}

// --------------------------------------------------------------------------
// helpers
// --------------------------------------------------------------------------
__device__ __forceinline__ uint32_t smem_u32(const void* p) {
    uint32_t a;
    asm("{ .reg .u64 t; cvta.to.shared.u64 t, %1; cvt.u32.u64 %0, t; }" : "=r"(a) : "l"(p));
    return a;
}

__device__ __forceinline__ void cp_async16(uint32_t saddr, const void* gptr) {
    asm volatile("cp.async.cg.shared.global [%0], [%1], 16;" :: "r"(saddr), "l"(gptr));
}

#define CP_COMMIT() asm volatile("cp.async.commit_group;" ::: "memory")
#define CP_WAIT2()  asm volatile("cp.async.wait_group 2;" ::: "memory")

#define LDSM4(r, addr)                                                         \
    asm volatile("ldmatrix.sync.aligned.m8n8.x4.shared.b16 {%0,%1,%2,%3}, [%4];" \
                 : "=r"((r)[0]), "=r"((r)[1]), "=r"((r)[2]), "=r"((r)[3])       \
                 : "r"(addr))

#define MMA16816(c, a, b0, b1)                                                 \
    asm volatile("mma.sync.aligned.m16n8k16.row.col.f32.f16.f16.f32 "          \
                 "{%0,%1,%2,%3}, {%4,%5,%6,%7}, {%8,%9}, {%0,%1,%2,%3};"       \
                 : "+f"((c)[0]), "+f"((c)[1]), "+f"((c)[2]), "+f"((c)[3])      \
                 : "r"((a)[0]), "r"((a)[1]), "r"((a)[2]), "r"((a)[3]),         \
                   "r"(b0), "r"(b1))

__device__ __forceinline__ uint32_t swz(uint32_t off) {
    return off ^ ((off >> 3) & 0x70u);   // 128B-row XOR swizzle
}

// --------------------------------------------------------------------------
// GEMM config: CTA 128x128, warp tile 64x32, BK=64, 3 stages, 2 CTAs/SM
// --------------------------------------------------------------------------
constexpr int BM = 128, BN = 128, BK = 64;
constexpr int NCHUNK = IN_F / BK;          // 16
constexpr int ASTG = BM * BK * 2;          // 16384 B (fp16)
constexpr int BSTG = BN * BK * 2;          // 16384 B
constexpr int STAGES = 3;
constexpr int SM_B    = STAGES * ASTG;               // 49152
constexpr int SM_BIAS = SM_B + STAGES * BSTG;        // 98304
constexpr int SM_TOTAL = SM_BIAS + 512;              // 98816 -> 2 CTAs/SM

__global__ void __launch_bounds__(256, 2)
qgemm(const float* __restrict__ x, const float* __restrict__ bias,
      float* __restrict__ out) {
    extern __shared__ __align__(1024) char smem[];
    const uint32_t sb = smem_u32(smem);
    const int tid  = threadIdx.x;
    const int lane = tid & 31;
    const int wid  = tid >> 5;
    const int warp_m = wid >> 2;            // 0..1  (64 rows each)
    const int warp_n = wid & 3;             // 0..3  (32 cols each)
    const int m_base = blockIdx.y * BM;
    const int n_base = blockIdx.x * BN;

    if (tid < 128) reinterpret_cast<float*>(smem + SM_BIAS)[tid] = bias[n_base + tid];

    // load geometry: 16B fp16 segment per thread-op, 128B rows, 32 rows/round
    const int seg  = tid & 7;               // 8 segs per 128B row
    const int row0 = tid >> 3;              // 0..31

    // A: fp32 gmem -> cvt fp16 -> STS.128 (swizzled). 4 rounds of 32 rows.
    auto load_a = [&](int s, int c) {
        const float* ga = x + (size_t)(m_base + row0) * IN_F + c * BK + seg * 8;
        char* base = smem + s * ASTG;
        #pragma unroll 2
        for (int r = 0; r < 4; r++) {
            const float4* p4 = reinterpret_cast<const float4*>(ga + (size_t)(r * 32) * IN_F);
            float4 fa = p4[0];
            float4 fb = p4[1];
            __half2 h0 = __floats2half2_rn(fa.x, fa.y);
            __half2 h1 = __floats2half2_rn(fa.z, fa.w);
            __half2 h2 = __floats2half2_rn(fb.x, fb.y);
            __half2 h3 = __floats2half2_rn(fb.z, fb.w);
            uint4 p;
            p.x = *reinterpret_cast<uint32_t*>(&h0);
            p.y = *reinterpret_cast<uint32_t*>(&h1);
            p.z = *reinterpret_cast<uint32_t*>(&h2);
            p.w = *reinterpret_cast<uint32_t*>(&h3);
            uint32_t off = swz((uint32_t)(row0 + r * 32) * 128u + (uint32_t)seg * 16u);
            *reinterpret_cast<uint4*>(base + off) = p;
        }
    };

    // B: fp16 weights via cp.async (4 rounds of 32 rows)
    auto load_b = [&](int s, int c) {
        const __half* gb = g_W + (size_t)(n_base + row0) * IN_F + c * BK + seg * 8;
        const uint32_t sB2 = sb + SM_B + s * BSTG;
        #pragma unroll
        for (int r = 0; r < 4; r++) {
            uint32_t off = swz((uint32_t)(row0 + r * 32) * 128u + (uint32_t)seg * 16u);
            cp_async16(sB2 + off, gb + (size_t)(r * 32) * IN_F);
        }
    };

    float acc[4][4][4] = {};

    // preload stages 0,1 (chunks 0,1)
    #pragma unroll
    for (int s = 0; s < 2; s++) {
        load_a(s, s);
        load_b(s, s);
        CP_COMMIT();
    }

    #pragma unroll 1
    for (int c = 0; c < NCHUNK; c++) {
        // barrier: all warps done reading stage (c-1)%3 == (c+2)%3; also makes
        // chunk c's A-STS (issued at iter c-2) visible (BAR drains STS).
        __syncthreads();
        // issue next loads BEFORE waiting on chunk c
        if (c + 2 < NCHUNK) {
            load_a((c + 2) % 3, c + 2);
            load_b((c + 2) % 3, c + 2);
        }
        CP_COMMIT();                // unconditional: uniform group counting
        CP_WAIT2();                 // all but newest 2 groups done -> B chunk c resident

        const int s = c % 3;
        const uint32_t sA  = sb + s * ASTG;
        const uint32_t sB2 = sb + SM_B + s * BSTG;

        #pragma unroll
        for (int ks = 0; ks < 4; ks++) {
            uint32_t a[4][4], b[2][4];
            #pragma unroll
            for (int mt = 0; mt < 4; mt++) {
                int row = warp_m * 64 + mt * 16 + (lane & 15);
                int col = ks * 16 + (lane >> 4) * 8;
                LDSM4(a[mt], sA + swz((uint32_t)row * 128u + (uint32_t)col * 2u));
            }
            #pragma unroll
            for (int nt = 0; nt < 2; nt++) {
                int row = warp_n * 32 + nt * 16 + (lane & 7) + ((lane >> 4) & 1) * 8;
                int col = ks * 16 + ((lane >> 3) & 1) * 8;
                LDSM4(b[nt], sB2 + swz((uint32_t)row * 128u + (uint32_t)col * 2u));
            }
            #pragma unroll
            for (int mt = 0; mt < 4; mt++) {
                #pragma unroll
                for (int no = 0; no < 4; no++) {
                    MMA16816(acc[mt][no], a[mt],
                             b[no >> 1][(no & 1) * 2], b[no >> 1][(no & 1) * 2 + 1]);
                }
            }
        }
    }

    // epilogue: direct float2 stores + bias
    const float* sbias = reinterpret_cast<const float*>(smem + SM_BIAS);
    #pragma unroll
    for (int mt = 0; mt < 4; mt++) {
        int r0 = m_base + warp_m * 64 + mt * 16 + (lane >> 2);
        #pragma unroll
        for (int no = 0; no < 4; no++) {
            int cl = warp_n * 32 + no * 8 + (lane & 3) * 2;   // local col
            float b0 = sbias[cl], b1 = sbias[cl + 1];
            float2 v0 = make_float2(acc[mt][no][0] + b0, acc[mt][no][1] + b1);
            float2 v1 = make_float2(acc[mt][no][2] + b0, acc[mt][no][3] + b1);
            *reinterpret_cast<float2*>(out + (size_t)r0 * OUT_F + n_base + cl)       = v0;
            *reinterpret_cast<float2*>(out + (size_t)(r0 + 8) * OUT_F + n_base + cl) = v1;
        }
    }
}

// --------------------------------------------------------------------------
extern "C" void kernel_launch(void* const* d_in, const int* in_sizes, int n_in,
                              void* d_out, int out_size) {
    const float* x    = (const float*)d_in[0];
    const float* rw   = (const float*)d_in[1];
    const float* iw   = (const float*)d_in[2];
    const float* jw   = (const float*)d_in[3];
    const float* kw   = (const float*)d_in[4];
    const float* bias = (const float*)d_in[5];
    float* out = (float*)d_out;

    static bool attr_done = false;
    if (!attr_done) {
        cudaFuncSetAttribute(qgemm, cudaFuncAttributeMaxDynamicSharedMemorySize, SM_TOTAL);
        attr_done = true;
    }

    build_w_kernel<<<OUT_F * 256 / 256, 256>>>(rw, iw, jw, kw);

    dim3 grid(OUT_F / BN, M_TOTAL / BM);   // (8, 256): N fastest -> A-tile L2 reuse
    qgemm<<<grid, 256, SM_TOTAL>>>(x, bias, out);
}

// round 8
// speedup vs baseline: 3.8216x; 1.3301x over previous
#include <cuda_runtime.h>
#include <cuda_fp16.h>
#include <cstdint>
#include <cstddef>

// ============================================================================
// QuaternionLinear == one dense GEMM: C[32768,1024] = X[32768,1024] @ W^T
//   W[4o+oc, 4i+ic] = S[oc][ic] * w_{T[oc][ic]}[o,i]
// compute_103 PTX rejects tcgen05.* -> cp.async + ldmatrix + mma.sync (HMMA).
// R8: warp tile 64x64 at low thread count: CTA 128 threads (2x2 warps),
// tile 128x128, BK=64, 3 stages, 2 CTAs/SM (256 regs/thr budget -> no spill),
// register fragment double-buffering across ks to hide LDSM latency.
// Crossbar per SM per chunk: 128KB LDSM + 64KB fill = 1536 cyc < 2048 tensor.
// ============================================================================

#define IN_F    1024
#define OUT_F   1024
#define M_TOTAL 32768

__device__ __half g_W[(size_t)OUT_F * IN_F];            // 2 MB
__device__ __half g_X[(size_t)M_TOTAL * IN_F];          // 64 MB scratch

__constant__ int   c_T[16] = {0,1,2,3,  1,0,3,2,  2,3,0,1,  3,2,1,0};
__constant__ float c_S[16] = {1,-1,-1,-1,  1,1,1,-1,  1,-1,1,1,  1,1,-1,1};

// --------------------------------------------------------------------------
// Fused prologue: blocks [0, 1024) build W; blocks [1024, 17408) convert X.
// --------------------------------------------------------------------------
constexpr int WBLOCKS = OUT_F * 256 / 256;                    // 1024
constexpr int XBLOCKS = (M_TOTAL * IN_F / 8) / 256;           // 16384

__global__ void prologue_kernel(const float* __restrict__ rw, const float* __restrict__ iw,
                                const float* __restrict__ jw, const float* __restrict__ kw,
                                const float* __restrict__ x) {
    if (blockIdx.x < WBLOCKS) {
        int idx = blockIdx.x * 256 + threadIdx.x;   // idx = n*256 + i
        int n = idx >> 8;
        int i = idx & 255;
        int o = n >> 2, oc = n & 3;
        const float* ws[4] = {rw, iw, jw, kw};
        float v0 = c_S[oc*4+0] * ws[c_T[oc*4+0]][o*256 + i];
        float v1 = c_S[oc*4+1] * ws[c_T[oc*4+1]][o*256 + i];
        float v2 = c_S[oc*4+2] * ws[c_T[oc*4+2]][o*256 + i];
        float v3 = c_S[oc*4+3] * ws[c_T[oc*4+3]][o*256 + i];
        __half2 h01 = __floats2half2_rn(v0, v1);
        __half2 h23 = __floats2half2_rn(v2, v3);
        uint2 p;
        p.x = *reinterpret_cast<uint32_t*>(&h01);
        p.y = *reinterpret_cast<uint32_t*>(&h23);
        *reinterpret_cast<uint2*>(&g_W[(size_t)n * IN_F + 4 * i]) = p;
    } else {
        size_t i = ((size_t)(blockIdx.x - WBLOCKS) * 256 + threadIdx.x) * 2;  // float4 idx
        #pragma unroll
        for (int j = 0; j < 2; j++) {
            float4 f = reinterpret_cast<const float4*>(x)[i + j];
            __half2 h0 = __floats2half2_rn(f.x, f.y);
            __half2 h1 = __floats2half2_rn(f.z, f.w);
            uint2 p;
            p.x = *reinterpret_cast<uint32_t*>(&h0);
            p.y = *reinterpret_cast<uint32_t*>(&h1);
            reinterpret_cast<uint2*>(g_X)[i + j] = p;
        }
    }
}

// --------------------------------------------------------------------------
// helpers
// --------------------------------------------------------------------------
__device__ __forceinline__ uint32_t smem_u32(const void* p) {
    uint32_t a;
    asm("{ .reg .u64 t; cvta.to.shared.u64 t, %1; cvt.u32.u64 %0, t; }" : "=r"(a) : "l"(p));
    return a;
}

__device__ __forceinline__ void cp_async16(uint32_t saddr, const void* gptr) {
    asm volatile("cp.async.cg.shared.global [%0], [%1], 16;" :: "r"(saddr), "l"(gptr));
}

#define CP_COMMIT() asm volatile("cp.async.commit_group;" ::: "memory")
#define CP_WAIT1()  asm volatile("cp.async.wait_group 1;" ::: "memory")

#define LDSM4(r, addr)                                                         \
    asm volatile("ldmatrix.sync.aligned.m8n8.x4.shared.b16 {%0,%1,%2,%3}, [%4];" \
                 : "=r"((r)[0]), "=r"((r)[1]), "=r"((r)[2]), "=r"((r)[3])       \
                 : "r"(addr))

#define MMA16816(c, a, b0, b1)                                                 \
    asm volatile("mma.sync.aligned.m16n8k16.row.col.f32.f16.f16.f32 "          \
                 "{%0,%1,%2,%3}, {%4,%5,%6,%7}, {%8,%9}, {%0,%1,%2,%3};"       \
                 : "+f"((c)[0]), "+f"((c)[1]), "+f"((c)[2]), "+f"((c)[3])      \
                 : "r"((a)[0]), "r"((a)[1]), "r"((a)[2]), "r"((a)[3]),         \
                   "r"(b0), "r"(b1))

__device__ __forceinline__ uint32_t swz(uint32_t off) {
    return off ^ ((off >> 3) & 0x70u);   // 128B-row XOR swizzle
}

// --------------------------------------------------------------------------
// GEMM config: CTA 128x128, 128 threads, warp tile 64x64, BK=64, 3 stages
// --------------------------------------------------------------------------
constexpr int BM = 128, BN = 128, BK = 64;
constexpr int NCHUNK = IN_F / BK;          // 16
constexpr int ASTG = BM * BK * 2;          // 16384 B
constexpr int BSTG = BN * BK * 2;          // 16384 B
constexpr int STAGES = 3;
constexpr int SM_B    = STAGES * ASTG;               // 49152
constexpr int SM_BIAS = SM_B + STAGES * BSTG;        // 98304
constexpr int SM_TOTAL = SM_BIAS + 512;              // 98816 -> 2 CTAs/SM

__global__ void __launch_bounds__(128, 2)
qgemm(const float* __restrict__ bias, float* __restrict__ out) {
    extern __shared__ __align__(1024) char smem[];
    const uint32_t sb = smem_u32(smem);
    const int tid  = threadIdx.x;
    const int lane = tid & 31;
    const int wid  = tid >> 5;              // 0..3
    const int warp_m = wid >> 1;            // 0..1  (64 rows)
    const int warp_n = wid & 1;             // 0..1  (64 cols)
    const int m_base = blockIdx.y * BM;
    const int n_base = blockIdx.x * BN;

    reinterpret_cast<float*>(smem + SM_BIAS)[tid] = bias[n_base + tid];

    // cp.async geometry: 128 threads, 16B per op, 128B rows, 16 rows/round
    const int seg  = tid & 7;               // 8 segs per 128B row
    const int row0 = tid >> 3;              // 0..15

    auto load_chunk = [&](int s, int c) {
        const int k0 = c * BK;
        const __half* ga = g_X + (size_t)(m_base + row0) * IN_F + k0 + seg * 8;
        const __half* gb = g_W + (size_t)(n_base + row0) * IN_F + k0 + seg * 8;
        const uint32_t sA  = sb + s * ASTG;
        const uint32_t sB2 = sb + SM_B + s * BSTG;
        #pragma unroll
        for (int r = 0; r < 8; r++) {       // A: 128 rows
            uint32_t off = swz((uint32_t)(row0 + r * 16) * 128u + (uint32_t)seg * 16u);
            cp_async16(sA  + off, ga + (size_t)(r * 16) * IN_F);
            cp_async16(sB2 + off, gb + (size_t)(r * 16) * IN_F);
        }
    };

    float acc[4][8][4] = {};

    #pragma unroll
    for (int s = 0; s < 2; s++) { load_chunk(s, s); CP_COMMIT(); }

    // fragment double buffers (ks ping-pong)
    uint32_t afr[2][4][4], bfr[2][4][4];

    auto ldsm_ks = [&](uint32_t sA, uint32_t sB2, int ks, int buf) {
        #pragma unroll
        for (int mt = 0; mt < 4; mt++) {
            int row = warp_m * 64 + mt * 16 + (lane & 15);
            int col = ks * 16 + (lane >> 4) * 8;
            LDSM4(afr[buf][mt], sA + swz((uint32_t)row * 128u + (uint32_t)col * 2u));
        }
        #pragma unroll
        for (int nt = 0; nt < 4; nt++) {
            int row = warp_n * 64 + nt * 16 + (lane & 7) + ((lane >> 4) & 1) * 8;
            int col = ks * 16 + ((lane >> 3) & 1) * 8;
            LDSM4(bfr[buf][nt], sB2 + swz((uint32_t)row * 128u + (uint32_t)col * 2u));
        }
    };

    #pragma unroll 1
    for (int c = 0; c < NCHUNK; c++) {
        CP_WAIT1();          // chunk c resident
        __syncthreads();     // + all warps done reading stage being refilled next
        if (c + 2 < NCHUNK) load_chunk((c + 2) % 3, c + 2);
        CP_COMMIT();

        const int s = c % 3;
        const uint32_t sA  = sb + s * ASTG;
        const uint32_t sB2 = sb + SM_B + s * BSTG;

        ldsm_ks(sA, sB2, 0, 0);
        #pragma unroll
        for (int ks = 0; ks < 4; ks++) {
            const int cur = ks & 1;
            if (ks < 3) ldsm_ks(sA, sB2, ks + 1, cur ^ 1);   // prefetch next frags
            #pragma unroll
            for (int mt = 0; mt < 4; mt++) {
                #pragma unroll
                for (int no = 0; no < 8; no++) {
                    MMA16816(acc[mt][no], afr[cur][mt],
                             bfr[cur][no >> 1][(no & 1) * 2],
                             bfr[cur][no >> 1][(no & 1) * 2 + 1]);
                }
            }
        }
    }

    // epilogue: direct float2 stores + bias
    const float* sbias = reinterpret_cast<const float*>(smem + SM_BIAS);
    #pragma unroll
    for (int mt = 0; mt < 4; mt++) {
        int r0 = m_base + warp_m * 64 + mt * 16 + (lane >> 2);
        #pragma unroll
        for (int no = 0; no < 8; no++) {
            int cl = warp_n * 64 + no * 8 + (lane & 3) * 2;   // local col
            float b0 = sbias[cl], b1 = sbias[cl + 1];
            float2 v0 = make_float2(acc[mt][no][0] + b0, acc[mt][no][1] + b1);
            float2 v1 = make_float2(acc[mt][no][2] + b0, acc[mt][no][3] + b1);
            *reinterpret_cast<float2*>(out + (size_t)r0 * OUT_F + n_base + cl)       = v0;
            *reinterpret_cast<float2*>(out + (size_t)(r0 + 8) * OUT_F + n_base + cl) = v1;
        }
    }
}

// --------------------------------------------------------------------------
extern "C" void kernel_launch(void* const* d_in, const int* in_sizes, int n_in,
                              void* d_out, int out_size) {
    const float* x    = (const float*)d_in[0];
    const float* rw   = (const float*)d_in[1];
    const float* iw   = (const float*)d_in[2];
    const float* jw   = (const float*)d_in[3];
    const float* kw   = (const float*)d_in[4];
    const float* bias = (const float*)d_in[5];
    float* out = (float*)d_out;

    static bool attr_done = false;
    if (!attr_done) {
        cudaFuncSetAttribute(qgemm, cudaFuncAttributeMaxDynamicSharedMemorySize, SM_TOTAL);
        attr_done = true;
    }

    prologue_kernel<<<WBLOCKS + XBLOCKS, 256>>>(rw, iw, jw, kw, x);

    dim3 grid(OUT_F / BN, M_TOTAL / BM);   // (8, 256): N fastest -> A-tile L2 reuse
    qgemm<<<grid, 128, SM_TOTAL>>>(bias, out);
}

// round 9
// speedup vs baseline: 3.9559x; 1.0352x over previous
#include <cuda_runtime.h>
#include <cuda_fp16.h>
#include <cstdint>
#include <cstddef>

// ============================================================================
// QuaternionLinear == one dense GEMM: C[32768,1024] = X[32768,1024] @ W^T
//   W[4o+oc, 4i+ic] = S[oc][ic] * w_{T[oc][ic]}[o,i]
// compute_103 PTX rejects tcgen05.* -> cp.async + ldmatrix + mma.sync (HMMA).
// R9: A staged in fp32 DIRECTLY from x via cp.async (X-convert prologue
// deleted); A fragments = swizzled LDS.64 + cvt.f16x2 in registers.
// CTA 128x128, 128 thr, warp 64x64, 2 stages (96KB), 2 CTAs/SM,
// fragment double-buffering across ks (R8's win, kept).
// ============================================================================

#define IN_F    1024
#define OUT_F   1024
#define M_TOTAL 32768

__device__ __half g_W[(size_t)OUT_F * IN_F];            // 2 MB

__constant__ int   c_T[16] = {0,1,2,3,  1,0,3,2,  2,3,0,1,  3,2,1,0};
__constant__ float c_S[16] = {1,-1,-1,-1,  1,1,1,-1,  1,-1,1,1,  1,1,-1,1};

__global__ void build_w_kernel(const float* __restrict__ rw, const float* __restrict__ iw,
                               const float* __restrict__ jw, const float* __restrict__ kw) {
    int idx = blockIdx.x * 256 + threadIdx.x;   // idx = n*256 + i
    int n = idx >> 8;
    int i = idx & 255;
    int o = n >> 2, oc = n & 3;
    const float* ws[4] = {rw, iw, jw, kw};
    float v0 = c_S[oc*4+0] * ws[c_T[oc*4+0]][o*256 + i];
    float v1 = c_S[oc*4+1] * ws[c_T[oc*4+1]][o*256 + i];
    float v2 = c_S[oc*4+2] * ws[c_T[oc*4+2]][o*256 + i];
    float v3 = c_S[oc*4+3] * ws[c_T[oc*4+3]][o*256 + i];
    __half2 h01 = __floats2half2_rn(v0, v1);
    __half2 h23 = __floats2half2_rn(v2, v3);
    uint2 p;
    p.x = *reinterpret_cast<uint32_t*>(&h01);
    p.y = *reinterpret_cast<uint32_t*>(&h23);
    *reinterpret_cast<uint2*>(&g_W[(size_t)n * IN_F + 4 * i]) = p;
}

// --------------------------------------------------------------------------
// helpers
// --------------------------------------------------------------------------
__device__ __forceinline__ uint32_t smem_u32(const void* p) {
    uint32_t a;
    asm("{ .reg .u64 t; cvta.to.shared.u64 t, %1; cvt.u32.u64 %0, t; }" : "=r"(a) : "l"(p));
    return a;
}

__device__ __forceinline__ void cp_async16(uint32_t saddr, const void* gptr) {
    asm volatile("cp.async.cg.shared.global [%0], [%1], 16;" :: "r"(saddr), "l"(gptr));
}

#define CP_COMMIT() asm volatile("cp.async.commit_group;" ::: "memory")
#define CP_WAIT0()  asm volatile("cp.async.wait_group 0;" ::: "memory")

#define LDSM4(r, addr)                                                         \
    asm volatile("ldmatrix.sync.aligned.m8n8.x4.shared.b16 {%0,%1,%2,%3}, [%4];" \
                 : "=r"((r)[0]), "=r"((r)[1]), "=r"((r)[2]), "=r"((r)[3])       \
                 : "r"(addr))

#define MMA16816(c, a, b0, b1)                                                 \
    asm volatile("mma.sync.aligned.m16n8k16.row.col.f32.f16.f16.f32 "          \
                 "{%0,%1,%2,%3}, {%4,%5,%6,%7}, {%8,%9}, {%0,%1,%2,%3};"       \
                 : "+f"((c)[0]), "+f"((c)[1]), "+f"((c)[2]), "+f"((c)[3])      \
                 : "r"((a)[0]), "r"((a)[1]), "r"((a)[2]), "r"((a)[3]),         \
                   "r"(b0), "r"(b1))

__device__ __forceinline__ uint32_t swzB(uint32_t off) {   // fp16 128B rows
    return off ^ ((off >> 3) & 0x70u);
}
// fp32 A, 256B rows: XOR 32B slot by row&7 -> 8-row column-segments conflict-free
__device__ __forceinline__ uint32_t swzA(uint32_t row, uint32_t bytecol) {
    return (row * 256u + bytecol) ^ ((row & 7u) << 5);
}

// --------------------------------------------------------------------------
// GEMM config: CTA 128x128, 128 threads, warp tile 64x64, BK=64, 2 stages
// A stage: fp32 32KB; B stage: fp16 16KB
// --------------------------------------------------------------------------
constexpr int BM = 128, BN = 128, BK = 64;
constexpr int NCHUNK = IN_F / BK;          // 16
constexpr int ASTG = BM * BK * 4;          // 32768 B (fp32)
constexpr int BSTG = BN * BK * 2;          // 16384 B (fp16)
constexpr int STAGES = 2;
constexpr int SM_B    = STAGES * ASTG;               // 65536
constexpr int SM_BIAS = SM_B + STAGES * BSTG;        // 98304
constexpr int SM_TOTAL = SM_BIAS + 512;              // 98816 -> 2 CTAs/SM

__global__ void __launch_bounds__(128, 2)
qgemm(const float* __restrict__ x, const float* __restrict__ bias,
      float* __restrict__ out) {
    extern __shared__ __align__(1024) char smem[];
    const uint32_t sb = smem_u32(smem);
    const int tid  = threadIdx.x;
    const int lane = tid & 31;
    const int wid  = tid >> 5;              // 0..3
    const int warp_m = wid >> 1;            // 0..1  (64 rows)
    const int warp_n = wid & 1;             // 0..1  (64 cols)
    const int m_base = blockIdx.y * BM;
    const int n_base = blockIdx.x * BN;

    reinterpret_cast<float*>(smem + SM_BIAS)[tid] = bias[n_base + tid];

    // cp.async geometry:
    //  A: fp32, 256B rows, 16 segs of 16B; 128 thr -> 8 rows/round, 16 rounds
    //  B: fp16, 128B rows,  8 segs of 16B; 16 rows/round, 8 rounds
    const int asegs = tid & 15;             // 0..15
    const int arow0 = tid >> 4;             // 0..7
    const int bseg  = tid & 7;              // 0..7
    const int brow0 = tid >> 3;             // 0..15

    auto load_chunk = [&](int s, int c) {
        const int k0 = c * BK;
        const float*  ga = x + (size_t)(m_base + arow0) * IN_F + k0 + asegs * 4;
        const __half* gb = g_W + (size_t)(n_base + brow0) * IN_F + k0 + bseg * 8;
        const uint32_t sA  = sb + s * ASTG;
        const uint32_t sB2 = sb + SM_B + s * BSTG;
        #pragma unroll
        for (int r = 0; r < 16; r++) {      // A: 128 rows fp32
            uint32_t row = (uint32_t)(arow0 + r * 8);
            cp_async16(sA + swzA(row, (uint32_t)asegs * 16u), ga + (size_t)(r * 8) * IN_F);
        }
        #pragma unroll
        for (int r = 0; r < 8; r++) {       // B: 128 rows fp16
            uint32_t off = swzB((uint32_t)(brow0 + r * 16) * 128u + (uint32_t)bseg * 16u);
            cp_async16(sB2 + off, gb + (size_t)(r * 16) * IN_F);
        }
    };

    float acc[4][8][4] = {};

    // fragment double buffers (ks ping-pong)
    uint32_t afr[2][4][4], bfr[2][4][4];

    // A fragments: LDS.64 fp32 pairs + cvt to half2 (matches mma layout)
    auto lda_ks = [&](const char* aBase, int ks, int buf) {
        #pragma unroll
        for (int mt = 0; mt < 4; mt++) {
            int r    = warp_m * 64 + mt * 16 + (lane >> 2);
            int bcol = (ks * 16 + (lane & 3) * 2) * 4;      // byte col
            float2 f0 = *reinterpret_cast<const float2*>(aBase + swzA(r,     bcol));
            float2 f1 = *reinterpret_cast<const float2*>(aBase + swzA(r + 8, bcol));
            float2 f2 = *reinterpret_cast<const float2*>(aBase + swzA(r,     bcol + 32));
            float2 f3 = *reinterpret_cast<const float2*>(aBase + swzA(r + 8, bcol + 32));
            __half2 h0 = __floats2half2_rn(f0.x, f0.y);
            __half2 h1 = __floats2half2_rn(f1.x, f1.y);
            __half2 h2 = __floats2half2_rn(f2.x, f2.y);
            __half2 h3 = __floats2half2_rn(f3.x, f3.y);
            afr[buf][mt][0] = *reinterpret_cast<uint32_t*>(&h0);
            afr[buf][mt][1] = *reinterpret_cast<uint32_t*>(&h1);
            afr[buf][mt][2] = *reinterpret_cast<uint32_t*>(&h2);
            afr[buf][mt][3] = *reinterpret_cast<uint32_t*>(&h3);
        }
    };

    auto ldb_ks = [&](uint32_t sB2, int ks, int buf) {
        #pragma unroll
        for (int nt = 0; nt < 4; nt++) {
            int row = warp_n * 64 + nt * 16 + (lane & 7) + ((lane >> 4) & 1) * 8;
            int col = ks * 16 + ((lane >> 3) & 1) * 8;
            LDSM4(bfr[buf][nt], sB2 + swzB((uint32_t)row * 128u + (uint32_t)col * 2u));
        }
    };

    load_chunk(0, 0);
    CP_COMMIT();

    #pragma unroll 1
    for (int c = 0; c < NCHUNK; c++) {
        CP_WAIT0();          // chunk c (only pending group) resident
        __syncthreads();     // visibility to all warps + stage (c+1)&1 free
        if (c + 1 < NCHUNK) { load_chunk((c + 1) & 1, c + 1); CP_COMMIT(); }

        const int s = c & 1;
        const char* aBase  = smem + s * ASTG;
        const uint32_t sB2 = sb + SM_B + s * BSTG;

        lda_ks(aBase, 0, 0);
        ldb_ks(sB2,   0, 0);
        #pragma unroll
        for (int ks = 0; ks < 4; ks++) {
            const int cur = ks & 1;
            if (ks < 3) {                     // prefetch next fragments
                lda_ks(aBase, ks + 1, cur ^ 1);
                ldb_ks(sB2,   ks + 1, cur ^ 1);
            }
            #pragma unroll
            for (int mt = 0; mt < 4; mt++) {
                #pragma unroll
                for (int no = 0; no < 8; no++) {
                    MMA16816(acc[mt][no], afr[cur][mt],
                             bfr[cur][no >> 1][(no & 1) * 2],
                             bfr[cur][no >> 1][(no & 1) * 2 + 1]);
                }
            }
        }
    }

    // epilogue: direct float2 stores + bias
    const float* sbias = reinterpret_cast<const float*>(smem + SM_BIAS);
    #pragma unroll
    for (int mt = 0; mt < 4; mt++) {
        int r0 = m_base + warp_m * 64 + mt * 16 + (lane >> 2);
        #pragma unroll
        for (int no = 0; no < 8; no++) {
            int cl = warp_n * 64 + no * 8 + (lane & 3) * 2;   // local col
            float b0 = sbias[cl], b1 = sbias[cl + 1];
            float2 v0 = make_float2(acc[mt][no][0] + b0, acc[mt][no][1] + b1);
            float2 v1 = make_float2(acc[mt][no][2] + b0, acc[mt][no][3] + b1);
            *reinterpret_cast<float2*>(out + (size_t)r0 * OUT_F + n_base + cl)       = v0;
            *reinterpret_cast<float2*>(out + (size_t)(r0 + 8) * OUT_F + n_base + cl) = v1;
        }
    }
}

// --------------------------------------------------------------------------
extern "C" void kernel_launch(void* const* d_in, const int* in_sizes, int n_in,
                              void* d_out, int out_size) {
    const float* x    = (const float*)d_in[0];
    const float* rw   = (const float*)d_in[1];
    const float* iw   = (const float*)d_in[2];
    const float* jw   = (const float*)d_in[3];
    const float* kw   = (const float*)d_in[4];
    const float* bias = (const float*)d_in[5];
    float* out = (float*)d_out;

    static bool attr_done = false;
    if (!attr_done) {
        cudaFuncSetAttribute(qgemm, cudaFuncAttributeMaxDynamicSharedMemorySize, SM_TOTAL);
        attr_done = true;
    }

    build_w_kernel<<<OUT_F * 256 / 256, 256>>>(rw, iw, jw, kw);

    dim3 grid(OUT_F / BN, M_TOTAL / BM);   // (8, 256): N fastest -> A-tile L2 reuse
    qgemm<<<grid, 128, SM_TOTAL>>>(x, bias, out);
}